// round 14
// baseline (speedup 1.0000x reference)
#include <cuda_runtime.h>

// ============================================================================
// PIFNode_25812753449785 — FINAL (session converged; validated R9/R10/R11/R13)
//
// Math: the T=8 integrate-and-fire scan has closed form
//   spikes = clamp(floor(x + 0.5f), 0, 8)
// (v0 = x + 0.5; v at step t is exactly v0 - t in fp32 over the relevant
// range; rel_err = 0.0 on every passing round).
//
// HW: pure HBM-bound stream, 205.5 MB in + 205.5 MB out (interface-mandated).
// Steady-state bound: total dur_us = 411 MB / ~6.27 TB/s ≈ 65.5 us — measured
// dur_us (65.5-65.6 across six rounds) sits on this DRAM traffic-conservation
// bound to within 0.2%. Eleven configurations (MLP {1,2,4,8}, width
// {128b,256b}, .cs/.cg, occ {49-88%}, flat/persistent) bracket the ceiling.
//
// Optimum: 2x 256-bit accesses/thread, evict-first .cs, flat grid,
// branch-free exact-tile main kernel (n8 = 12544 * 512 exactly -> 1 launch).
// kernel 57.0-57.9us over four runs, DRAM ~76%, HBM 6200-6265 GB/s.
// ============================================================================

#define TPB 256
#define VPT8 2                      // 256-bit accesses per thread
#define TILE8 (TPB * VPT8)          // float8-units per block = 512

__device__ __forceinline__ void ld256_cs(const float* __restrict__ p, float* r) {
    asm("ld.global.cs.v8.f32 {%0,%1,%2,%3,%4,%5,%6,%7}, [%8];"
        : "=f"(r[0]), "=f"(r[1]), "=f"(r[2]), "=f"(r[3]),
          "=f"(r[4]), "=f"(r[5]), "=f"(r[6]), "=f"(r[7])
        : "l"(p));
}

__device__ __forceinline__ void st256_cs(float* __restrict__ p, const float* r) {
    asm volatile("st.global.cs.v8.f32 [%0], {%1,%2,%3,%4,%5,%6,%7,%8};"
        :: "l"(p),
           "f"(r[0]), "f"(r[1]), "f"(r[2]), "f"(r[3]),
           "f"(r[4]), "f"(r[5]), "f"(r[6]), "f"(r[7])
        : "memory");
}

__device__ __forceinline__ float pif1(float v) {
    return fminf(fmaxf(floorf(v + 0.5f), 0.0f), 8.0f);
}

// Full tiles only — zero predication, compile-time offsets.
__global__ void __launch_bounds__(TPB) pif_main(const float* __restrict__ x,
                                                float* __restrict__ out) {
    // index in 32-byte (float8) units
    long long base = (long long)blockIdx.x * TILE8 + threadIdx.x;

    float a[8], b[8];
    ld256_cs(x + base * 8, a);                       // 2 independent LDG.256
    ld256_cs(x + (base + TPB) * 8, b);

    float ra[8], rb[8];
    #pragma unroll
    for (int i = 0; i < 8; i++) ra[i] = pif1(a[i]);
    #pragma unroll
    for (int i = 0; i < 8; i++) rb[i] = pif1(b[i]);

    st256_cs(out + base * 8, ra);
    st256_cs(out + (base + TPB) * 8, rb);
}

// Ragged edge (float4 granularity) — not hit for this shape, kept for safety.
__global__ void pif_edge4(const float4* __restrict__ x, float4* __restrict__ out,
                          int start, int n4) {
    int i = start + blockIdx.x * blockDim.x + threadIdx.x;
    if (i < n4) {
        float4 v = __ldcs(x + i);
        float4 r;
        r.x = pif1(v.x); r.y = pif1(v.y); r.z = pif1(v.z); r.w = pif1(v.w);
        __stcs(out + i, r);
    }
}

// Ragged edge (scalar granularity) — not hit for this shape, kept for safety.
__global__ void pif_tail(const float* __restrict__ x, float* __restrict__ out,
                         int start, int n) {
    int i = start + blockIdx.x * blockDim.x + threadIdx.x;
    if (i < n) out[i] = pif1(x[i]);
}

extern "C" void kernel_launch(void* const* d_in, const int* in_sizes, int n_in,
                              void* d_out, int out_size) {
    const float* x = (const float*)d_in[0];
    float* out = (float*)d_out;
    int n = in_sizes[0];

    int n8 = n / 8;                                  // float8 units
    int full_blocks = n8 / TILE8;
    if (full_blocks > 0) {
        pif_main<<<full_blocks, TPB>>>(x, out);
    }
    int done4 = full_blocks * TILE8 * 2;             // in float4 units
    int n4 = n / 4;
    if (done4 < n4) {
        int rem = n4 - done4;
        pif_edge4<<<(rem + TPB - 1) / TPB, TPB>>>((const float4*)x, (float4*)out,
                                                  done4, n4);
    }
    int rem_start = n4 * 4;
    if (rem_start < n) {
        int rem = n - rem_start;
        pif_tail<<<(rem + TPB - 1) / TPB, TPB>>>(x, out, rem_start, rem);
    }
}

// round 15
// speedup vs baseline: 1.0010x; 1.0010x over previous
#include <cuda_runtime.h>

// ============================================================================
// PIFNode_25812753449785 — FINAL (session closed; validated R9/R10/R11/R13/R14)
//
// Math: the T=8 integrate-and-fire scan has closed form
//   spikes = clamp(floor(x + 0.5f), 0, 8)
// (v0 = x + 0.5; v at step t is exactly v0 - t in fp32 over the relevant
// range; rel_err = 0.0 on every passing round).
//
// HW: pure HBM-bound stream, 205.5 MB in + 205.5 MB out (interface-mandated).
// Conservation bound: dur_us >= 411 MB / ~6.27 TB/s ≈ 65.5 us. Measured
// 65.5-65.6 us across six passing rounds — bound attained to within 0.2%.
// Eleven configurations (MLP {1,2,4,8}, width {128b,256b}, .cs/.cg,
// occ {49-88%}, flat/persistent) confirm the ceiling from every direction.
//
// Optimum: 2x 256-bit accesses/thread, evict-first .cs, flat grid,
// branch-free exact-tile main kernel (n8 = 12544 * 512 exactly -> 1 launch).
// kernel 57.0-57.9us over five runs, DRAM ~76%, HBM 6200-6265 GB/s.
// ============================================================================

#define TPB 256
#define VPT8 2                      // 256-bit accesses per thread
#define TILE8 (TPB * VPT8)          // float8-units per block = 512

__device__ __forceinline__ void ld256_cs(const float* __restrict__ p, float* r) {
    asm("ld.global.cs.v8.f32 {%0,%1,%2,%3,%4,%5,%6,%7}, [%8];"
        : "=f"(r[0]), "=f"(r[1]), "=f"(r[2]), "=f"(r[3]),
          "=f"(r[4]), "=f"(r[5]), "=f"(r[6]), "=f"(r[7])
        : "l"(p));
}

__device__ __forceinline__ void st256_cs(float* __restrict__ p, const float* r) {
    asm volatile("st.global.cs.v8.f32 [%0], {%1,%2,%3,%4,%5,%6,%7,%8};"
        :: "l"(p),
           "f"(r[0]), "f"(r[1]), "f"(r[2]), "f"(r[3]),
           "f"(r[4]), "f"(r[5]), "f"(r[6]), "f"(r[7])
        : "memory");
}

__device__ __forceinline__ float pif1(float v) {
    return fminf(fmaxf(floorf(v + 0.5f), 0.0f), 8.0f);
}

// Full tiles only — zero predication, compile-time offsets.
__global__ void __launch_bounds__(TPB) pif_main(const float* __restrict__ x,
                                                float* __restrict__ out) {
    // index in 32-byte (float8) units
    long long base = (long long)blockIdx.x * TILE8 + threadIdx.x;

    float a[8], b[8];
    ld256_cs(x + base * 8, a);                       // 2 independent LDG.256
    ld256_cs(x + (base + TPB) * 8, b);

    float ra[8], rb[8];
    #pragma unroll
    for (int i = 0; i < 8; i++) ra[i] = pif1(a[i]);
    #pragma unroll
    for (int i = 0; i < 8; i++) rb[i] = pif1(b[i]);

    st256_cs(out + base * 8, ra);
    st256_cs(out + (base + TPB) * 8, rb);
}

// Ragged edge (float4 granularity) — not hit for this shape, kept for safety.
__global__ void pif_edge4(const float4* __restrict__ x, float4* __restrict__ out,
                          int start, int n4) {
    int i = start + blockIdx.x * blockDim.x + threadIdx.x;
    if (i < n4) {
        float4 v = __ldcs(x + i);
        float4 r;
        r.x = pif1(v.x); r.y = pif1(v.y); r.z = pif1(v.z); r.w = pif1(v.w);
        __stcs(out + i, r);
    }
}

// Ragged edge (scalar granularity) — not hit for this shape, kept for safety.
__global__ void pif_tail(const float* __restrict__ x, float* __restrict__ out,
                         int start, int n) {
    int i = start + blockIdx.x * blockDim.x + threadIdx.x;
    if (i < n) out[i] = pif1(x[i]);
}

extern "C" void kernel_launch(void* const* d_in, const int* in_sizes, int n_in,
                              void* d_out, int out_size) {
    const float* x = (const float*)d_in[0];
    float* out = (float*)d_out;
    int n = in_sizes[0];

    int n8 = n / 8;                                  // float8 units
    int full_blocks = n8 / TILE8;
    if (full_blocks > 0) {
        pif_main<<<full_blocks, TPB>>>(x, out);
    }
    int done4 = full_blocks * TILE8 * 2;             // in float4 units
    int n4 = n / 4;
    if (done4 < n4) {
        int rem = n4 - done4;
        pif_edge4<<<(rem + TPB - 1) / TPB, TPB>>>((const float4*)x, (float4*)out,
                                                  done4, n4);
    }
    int rem_start = n4 * 4;
    if (rem_start < n) {
        int rem = n - rem_start;
        pif_tail<<<(rem + TPB - 1) / TPB, TPB>>>(x, out, rem_start, rem);
    }
}